// round 4
// baseline (speedup 1.0000x reference)
#include <cuda_runtime.h>
#include <cuda_bf16.h>
#include <float.h>

// Problem constants
#define BATCH   4096
#define NVIEW   20
#define CDIM    512
#define HID     256
#define NCLS    40
#define SEL     8

#define VROWS   (BATCH * NVIEW)        // 81920 view rows
#define TROWS   (VROWS + BATCH)        // 86016 total MLP rows

// Output layout (tuple flattened: F_new, score, vertices_new)
#define FNEW_OFF   0
#define FNEW_CNT   (BATCH * SEL * CDIM)          // 16777216
#define SCORE_OFF  FNEW_CNT
#define SCORE_CNT  (BATCH * NVIEW * NCLS)        // 3276800
#define VNEW_OFF   (SCORE_OFF + SCORE_CNT)       // 20054016

// GEMM tiling
#define BM 64
#define BK 32

// smem layout (floats): [ sW2: 40x260 ][ union: max(A 64x32 + B 32x256, H 64x260) ]
#define W2_STRIDE  260
#define W2_FLOATS  (NCLS * W2_STRIDE)            // 10400
#define H_STRIDE   260
#define H_FLOATS   (BM * H_STRIDE)               // 16640
#define A_FLOATS   (BM * BK)                     // 2048
#define SMEM_FLOATS (W2_FLOATS + H_FLOATS)       // 27040
#define SMEM_BYTES  (SMEM_FLOATS * 4)            // 108160

// Scratch (device globals — no allocations allowed)
__device__ float g_pooled[BATCH * CDIM];
__device__ int   g_pred[BATCH];

// ---------------------------------------------------------------------------
// Kernel A: pooled_F[b,c] = sum_n F0[b,n,c] / 20
// ---------------------------------------------------------------------------
__global__ void pool_kernel(const float* __restrict__ F0) {
    int i = blockIdx.x * blockDim.x + threadIdx.x;      // over BATCH*128 float4
    int b  = i >> 7;
    int c4 = i & 127;
    const float4* p = reinterpret_cast<const float4*>(F0) + (size_t)b * (NVIEW * 128) + c4;
    float4 s = p[0];
#pragma unroll
    for (int n = 1; n < NVIEW; n++) {
        float4 q = p[n * 128];
        s.x += q.x; s.y += q.y; s.z += q.z; s.w += q.w;
    }
    const float inv = 1.0f / 20.0f;
    float4 o; o.x = s.x * inv; o.y = s.y * inv; o.z = s.z * inv; o.w = s.w * inv;
    reinterpret_cast<float4*>(g_pooled)[i] = o;
}

// ---------------------------------------------------------------------------
// Kernel B: fused MLP.  Rows [0,81920) = F0 rows -> score out.
//                       Rows [81920,86016) = pooled rows -> argmax -> g_pred.
// Block: 256 threads, 64 rows. GEMM1: 8x8 micro-tile per thread.
// ---------------------------------------------------------------------------
__global__ __launch_bounds__(256, 2)
void mlp_kernel(const float* __restrict__ F0,
                const float* __restrict__ W1,
                const float* __restrict__ bias1,
                const float* __restrict__ W2,
                const float* __restrict__ bias2,
                float* __restrict__ score_out) {
    extern __shared__ float smem[];
    float* sW2 = smem;                 // [40][260], sW2[col*260+k] = W2[k][col]
    float* uni = smem + W2_FLOATS;
    float* As  = uni;                  // [64][32] row-major
    float* Bs  = uni + A_FLOATS;       // [32][256] k-major
    float* H   = uni;                  // [64][260] (aliases A/B after GEMM1)

    const int t  = threadIdx.x;
    const int tx = t & 31;             // col group (32)
    const int ty = t >> 5;             // row group / warp (8)

    const int blockRow = blockIdx.x * BM;
    const bool pooled  = (blockRow >= VROWS);
    const float* Xbase = pooled ? (g_pooled + (size_t)(blockRow - VROWS) * CDIM)
                                : (F0 + (size_t)blockRow * CDIM);

    // Load transposed W2 into smem (one-time)
    for (int idx = t; idx < HID * NCLS; idx += 256) {
        int k = idx / NCLS, col = idx - k * NCLS;
        sW2[col * W2_STRIDE + k] = W2[idx];
    }

    // ---- GEMM1: acc[8][8] ----
    float acc[8][8];
#pragma unroll
    for (int r = 0; r < 8; r++) {
#pragma unroll
        for (int c = 0; c < 4; c++) {
            acc[r][c]     = bias1[tx * 4 + c];
            acc[r][c + 4] = bias1[128 + tx * 4 + c];
        }
    }

    const int ar = t >> 3;     // A-load row (0..31)
    const int aq = t & 7;      // A-load float4 chunk (0..7)

    for (int kt = 0; kt < CDIM / BK; kt++) {
        __syncthreads();
        // A tile: 64 rows x 32 floats (conflict-free contiguous STS.128)
        *reinterpret_cast<float4*>(&As[ar * BK + aq * 4]) =
            *reinterpret_cast<const float4*>(&Xbase[(size_t)ar * CDIM + kt * BK + aq * 4]);
        *reinterpret_cast<float4*>(&As[(ar + 32) * BK + aq * 4]) =
            *reinterpret_cast<const float4*>(&Xbase[(size_t)(ar + 32) * CDIM + kt * BK + aq * 4]);
        // B tile: 32x256 contiguous block of W1
        const float* Wk = W1 + (size_t)kt * BK * HID;
#pragma unroll
        for (int i = 0; i < 8; i++) {
            int idx = (t + i * 256) * 4;
            *reinterpret_cast<float4*>(&Bs[idx]) =
                *reinterpret_cast<const float4*>(&Wk[idx]);
        }
        __syncthreads();

#pragma unroll 4
        for (int k = 0; k < BK; k += 2) {
            float2 a2[8];
#pragma unroll
            for (int r = 0; r < 8; r++)
                a2[r] = *reinterpret_cast<const float2*>(&As[(ty * 8 + r) * BK + k]);
            float4 b00 = *reinterpret_cast<const float4*>(&Bs[k * HID + tx * 4]);
            float4 b01 = *reinterpret_cast<const float4*>(&Bs[k * HID + 128 + tx * 4]);
            float4 b10 = *reinterpret_cast<const float4*>(&Bs[(k + 1) * HID + tx * 4]);
            float4 b11 = *reinterpret_cast<const float4*>(&Bs[(k + 1) * HID + 128 + tx * 4]);
#pragma unroll
            for (int r = 0; r < 8; r++) {
                acc[r][0] += a2[r].x * b00.x; acc[r][1] += a2[r].x * b00.y;
                acc[r][2] += a2[r].x * b00.z; acc[r][3] += a2[r].x * b00.w;
                acc[r][4] += a2[r].x * b01.x; acc[r][5] += a2[r].x * b01.y;
                acc[r][6] += a2[r].x * b01.z; acc[r][7] += a2[r].x * b01.w;
                acc[r][0] += a2[r].y * b10.x; acc[r][1] += a2[r].y * b10.y;
                acc[r][2] += a2[r].y * b10.z; acc[r][3] += a2[r].y * b10.w;
                acc[r][4] += a2[r].y * b11.x; acc[r][5] += a2[r].y * b11.y;
                acc[r][6] += a2[r].y * b11.z; acc[r][7] += a2[r].y * b11.w;
            }
        }
    }
    __syncthreads();   // all A/B reads complete -> safe to alias H

    // LeakyReLU + write H [64][260]
#pragma unroll
    for (int r = 0; r < 8; r++) {
        int row = ty * 8 + r;
        float4 h0, h1;
        float v;
        v = acc[r][0]; h0.x = v > 0.f ? v : 0.2f * v;
        v = acc[r][1]; h0.y = v > 0.f ? v : 0.2f * v;
        v = acc[r][2]; h0.z = v > 0.f ? v : 0.2f * v;
        v = acc[r][3]; h0.w = v > 0.f ? v : 0.2f * v;
        v = acc[r][4]; h1.x = v > 0.f ? v : 0.2f * v;
        v = acc[r][5]; h1.y = v > 0.f ? v : 0.2f * v;
        v = acc[r][6]; h1.z = v > 0.f ? v : 0.2f * v;
        v = acc[r][7]; h1.w = v > 0.f ? v : 0.2f * v;
        *reinterpret_cast<float4*>(&H[row * H_STRIDE + tx * 4]) = h0;
        *reinterpret_cast<float4*>(&H[row * H_STRIDE + 128 + tx * 4]) = h1;
    }
    __syncthreads();

    // ---- GEMM2: 64x40 = H[64][256] @ W2 ----  thread: 2 rows x 5 cols
    const int rg = t >> 3;     // 0..31 -> rows rg*2, rg*2+1
    const int cg = t & 7;      // 0..7  -> cols cg*5..cg*5+4
    float s[2][5];
#pragma unroll
    for (int j = 0; j < 5; j++) { s[0][j] = bias2[cg * 5 + j]; s[1][j] = s[0][j]; }

#pragma unroll 4
    for (int k = 0; k < HID; k += 4) {
        float4 hA = *reinterpret_cast<const float4*>(&H[(rg * 2) * H_STRIDE + k]);
        float4 hB = *reinterpret_cast<const float4*>(&H[(rg * 2 + 1) * H_STRIDE + k]);
#pragma unroll
        for (int j = 0; j < 5; j++) {
            float4 w = *reinterpret_cast<const float4*>(&sW2[(cg * 5 + j) * W2_STRIDE + k]);
            s[0][j] += hA.x * w.x; s[0][j] += hA.y * w.y;
            s[0][j] += hA.z * w.z; s[0][j] += hA.w * w.w;
            s[1][j] += hB.x * w.x; s[1][j] += hB.y * w.y;
            s[1][j] += hB.z * w.z; s[1][j] += hB.w * w.w;
        }
    }
    __syncthreads();   // all H reads done -> reuse region for score tile

    // Stage score tile [64][40] (flat) in smem
#pragma unroll
    for (int rr = 0; rr < 2; rr++)
#pragma unroll
        for (int j = 0; j < 5; j++)
            H[(rg * 2 + rr) * NCLS + cg * 5 + j] = s[rr][j];
    __syncthreads();

    if (!pooled) {
        // Coalesced copy: 64 rows x 40 contiguous floats
        float* dst = score_out + (size_t)blockRow * NCLS;
        for (int idx = t; idx < BM * NCLS; idx += 256)
            dst[idx] = H[idx];
    } else {
        if (t < BM) {
            const float* row = &H[t * NCLS];
            float best = row[0]; int bi = 0;
#pragma unroll
            for (int i = 1; i < NCLS; i++)
                if (row[i] > best) { best = row[i]; bi = i; }   // strict > : first max (argmax ties)
            g_pred[blockRow - VROWS + t] = bi;
        }
    }
}

// ---------------------------------------------------------------------------
// Kernel C: per-batch top-8 (top_k semantics: desc, ties -> lower index) + gather
// ---------------------------------------------------------------------------
__global__ __launch_bounds__(256)
void select_kernel(const float* __restrict__ F0,
                   const float* __restrict__ V0,
                   const float* __restrict__ score,
                   float* __restrict__ Fnew,
                   float* __restrict__ Vnew) {
    const int b = blockIdx.x;
    const int t = threadIdx.x;
    __shared__ int sidx[SEL];

    if (t < 32) {
        int pred = g_pred[b];
        float v = (t < NVIEW) ? score[((size_t)b * NVIEW + t) * NCLS + pred] : -FLT_MAX;
        int myn = t;
#pragma unroll
        for (int sstep = 0; sstep < SEL; sstep++) {
            float bv = v; int bi = myn;
#pragma unroll
            for (int off = 16; off > 0; off >>= 1) {
                float ov = __shfl_down_sync(0xffffffffu, bv, off);
                int   oi = __shfl_down_sync(0xffffffffu, bi, off);
                if (ov > bv || (ov == bv && oi < bi)) { bv = ov; bi = oi; }
            }
            bi = __shfl_sync(0xffffffffu, bi, 0);
            if (t == 0) sidx[sstep] = bi;
            if (myn == bi) v = -FLT_MAX;
        }
    }
    __syncthreads();

    // F_new: 8 rows x 128 float4 (1024 float4 per block; 256 threads -> 4 iters)
    const float4* Fsrc = reinterpret_cast<const float4*>(F0);
    float4* Fdst = reinterpret_cast<float4*>(Fnew);
    for (int i = t; i < SEL * 128; i += 256) {
        int srow = i >> 7, c = i & 127;
        Fdst[((size_t)b * SEL + srow) * 128 + c] =
            Fsrc[((size_t)b * NVIEW + sidx[srow]) * 128 + c];
    }
    // vertices_new: 8 x 3
    if (t < SEL * 3) {
        int srow = t / 3, cmp = t - srow * 3;
        Vnew[(size_t)b * (SEL * 3) + t] = V0[(size_t)b * (NVIEW * 3) + sidx[srow] * 3 + cmp];
    }
}

// ---------------------------------------------------------------------------
extern "C" void kernel_launch(void* const* d_in, const int* in_sizes, int n_in,
                              void* d_out, int out_size) {
    (void)in_sizes; (void)n_in; (void)out_size;
    const float* F0 = (const float*)d_in[0];
    const float* V0 = (const float*)d_in[1];
    const float* W1 = (const float*)d_in[2];
    const float* b1 = (const float*)d_in[3];
    const float* W2 = (const float*)d_in[4];
    const float* b2 = (const float*)d_in[5];
    float* out   = (float*)d_out;
    float* Fnew  = out + FNEW_OFF;
    float* score = out + SCORE_OFF;
    float* Vnew  = out + VNEW_OFF;

    cudaFuncSetAttribute(mlp_kernel, cudaFuncAttributeMaxDynamicSharedMemorySize, SMEM_BYTES);

    pool_kernel<<<(BATCH * 128) / 256, 256>>>(F0);
    mlp_kernel<<<TROWS / BM, 256, SMEM_BYTES>>>(F0, W1, b1, W2, b2, score);
    select_kernel<<<BATCH, 256>>>(F0, V0, score, Fnew, Vnew);
}

// round 6
// speedup vs baseline: 1.4052x; 1.4052x over previous
#include <cuda_runtime.h>
#include <cuda_bf16.h>
#include <float.h>
#include <stdint.h>

// ============================ problem constants ============================
#define BATCH   4096
#define NVIEW   20
#define CDIM    512
#define HID     256
#define NCLS    40
#define SEL     8

#define VROWS   (BATCH * NVIEW)        // 81920
#define TROWS   (VROWS + BATCH)        // 86016

#define FNEW_OFF   0
#define FNEW_CNT   (BATCH * SEL * CDIM)
#define SCORE_OFF  FNEW_CNT
#define SCORE_CNT  (BATCH * NVIEW * NCLS)
#define VNEW_OFF   (SCORE_OFF + SCORE_CNT)

// ============================ mma.sync GEMM config =========================
// BM=128 rows/CTA, BN=256 (full HID). 8 warps (4 row-groups x 2 col-groups).
// Warp tile 32x128 = 2 m-tiles(16) x 16 n-tiles(8). K chunks of 32 (4 ksteps).
#define BMT       128
#define KCHUNK    32
#define NCHUNKS   (CDIM / KCHUNK)      // 16
#define A_PAD     36                   // floats per row (bank-conflict-free frags)

// smem byte offsets (mainloop double-buffer)
#define OFF_A0    0
#define A_STAGE   (BMT * A_PAD * 4)    // 18432
#define OFF_A1    A_STAGE
#define OFF_B0    (2 * A_STAGE)        // 36864
#define B_STAGE   65536                // 4 ksteps x 256n x 4kk x 16B
#define OFF_B1    (OFF_B0 + B_STAGE)   // 102400
// epilogue region (reuses everything): H [128][260] fp32, then W2^T [40][260]
#define H_STRIDE  260
#define OFF_H     0
#define OFF_W2    (BMT * H_STRIDE * 4)            // 133120
#define SMEM_BYTES (OFF_W2 + NCLS * H_STRIDE * 4) // 174720

// ============================ device scratch ===============================
__device__ float    g_pooled[BATCH * CDIM];
__device__ int      g_pred[BATCH];
// W1^T split into tf32 hi/lo, packed per (kstep, n, kk) as 16B quads:
//   quad[ks][n][kk] = { hi[k0+kk, n], hi[k0+kk+4, n], lo[k0+kk, n], lo[k0+kk+4, n] }
// with k0 = ks*8. 64 ksteps x 256 n x 4 kk x 4 words = 1 MB.
__device__ uint32_t g_w1p[64 * 1024 * 4];

// ============================ helpers ======================================
__device__ __forceinline__ uint32_t smem_u32(const void* p) {
    uint32_t a;
    asm("{ .reg .u64 t; cvta.to.shared.u64 t, %1; cvt.u32.u64 %0, t; }" : "=r"(a) : "l"(p));
    return a;
}
__device__ __forceinline__ void tf32split(float x, uint32_t& hi, uint32_t& lo) {
    asm("cvt.rna.tf32.f32 %0, %1;" : "=r"(hi) : "f"(x));
    float r = x - __uint_as_float(hi);
    asm("cvt.rna.tf32.f32 %0, %1;" : "=r"(lo) : "f"(r));
}
__device__ __forceinline__ void mma_tf32(float* d, const uint32_t* a, uint32_t b0, uint32_t b1) {
    asm volatile(
        "mma.sync.aligned.m16n8k8.row.col.f32.tf32.tf32.f32 "
        "{%0,%1,%2,%3}, {%4,%5,%6,%7}, {%8,%9}, {%0,%1,%2,%3};"
        : "+f"(d[0]), "+f"(d[1]), "+f"(d[2]), "+f"(d[3])
        : "r"(a[0]), "r"(a[1]), "r"(a[2]), "r"(a[3]), "r"(b0), "r"(b1));
}
__device__ __forceinline__ void cpasync16(uint32_t dst, const void* src) {
    asm volatile("cp.async.cg.shared.global [%0], [%1], 16;" :: "r"(dst), "l"(src));
}
#define CP_COMMIT()  asm volatile("cp.async.commit_group;" ::: "memory")
#define CP_WAIT(N)   asm volatile("cp.async.wait_group %0;" :: "n"(N) : "memory")

// ---------------------------------------------------------------------------
// Kernel A: pooled_F = mean over views (77.7% DRAM in R4 — keep)
// ---------------------------------------------------------------------------
__global__ void pool_kernel(const float* __restrict__ F0) {
    int i = blockIdx.x * blockDim.x + threadIdx.x;
    int b  = i >> 7;
    int c4 = i & 127;
    const float4* p = reinterpret_cast<const float4*>(F0) + (size_t)b * (NVIEW * 128) + c4;
    float4 s = p[0];
#pragma unroll
    for (int n = 1; n < NVIEW; n++) {
        float4 q = p[n * 128];
        s.x += q.x; s.y += q.y; s.z += q.z; s.w += q.w;
    }
    const float inv = 1.0f / 20.0f;
    float4 o; o.x = s.x * inv; o.y = s.y * inv; o.z = s.z * inv; o.w = s.w * inv;
    reinterpret_cast<float4*>(g_pooled)[i] = o;
}

// ---------------------------------------------------------------------------
// Kernel P: split W1 into tf32 hi/lo quads in the exact smem streaming layout
// W1 row-major [512][256]; i = k*256 + n -> coalesced reads.
// ---------------------------------------------------------------------------
__global__ void prep_w1_kernel(const float* __restrict__ W1) {
    int i = blockIdx.x * blockDim.x + threadIdx.x;   // over 512*256
    int k = i >> 8;
    int n = i & 255;
    uint32_t hi, lo;
    tf32split(W1[i], hi, lo);
    int ks = k >> 3;
    int kk = k & 7;
    uint32_t* q = g_w1p + ((size_t)ks * 1024 + n * 4 + (kk & 3)) * 4;
    if (kk < 4) { q[0] = hi; q[2] = lo; }
    else        { q[1] = hi; q[3] = lo; }
}

// ---------------------------------------------------------------------------
// Kernel B: 3xTF32 mma.sync MLP. 672 CTAs x 128 rows; CTAs >= 640 are pooled.
// ---------------------------------------------------------------------------
__global__ __launch_bounds__(256, 1)
void mlp_mma_kernel(const float* __restrict__ F0,
                    const float* __restrict__ bias1,
                    const float* __restrict__ W2,
                    const float* __restrict__ bias2,
                    float* __restrict__ score_out) {
    extern __shared__ char smem[];
    const uint32_t sb = smem_u32(smem);
    const int t   = threadIdx.x;
    const int wid = t >> 5;
    const int l   = t & 31;
    const int wr  = wid >> 1;          // 0..3 -> rows wr*32
    const int wc  = wid & 1;           // 0..1 -> cols wc*128

    const int blockRow = blockIdx.x * BMT;
    const bool pooled  = (blockRow >= VROWS);
    const float* Xbase = pooled ? (g_pooled + (size_t)(blockRow - VROWS) * CDIM)
                                : (F0 + (size_t)blockRow * CDIM);

    // ---- accumulators, initialized from bias1 (per-column) ----
    float acc[2][16][4];
#pragma unroll
    for (int nt = 0; nt < 16; nt++) {
        int n0 = wc * 128 + nt * 8 + 2 * (l & 3);
        float b0v = bias1[n0], b1v = bias1[n0 + 1];
#pragma unroll
        for (int mt = 0; mt < 2; mt++) {
            acc[mt][nt][0] = b0v; acc[mt][nt][1] = b1v;
            acc[mt][nt][2] = b0v; acc[mt][nt][3] = b1v;
        }
    }

    // ---- async chunk loader ----
    auto load_chunk = [&](int stage, int c) {
        uint32_t dA = sb + (stage ? OFF_A1 : OFF_A0);
        uint32_t dB = sb + (stage ? OFF_B1 : OFF_B0);
        // A: 128 rows x 32 floats = 1024 x 16B
#pragma unroll
        for (int j = 0; j < 4; j++) {
            int o = t + j * 256;
            int row = o >> 3, seg = o & 7;
            cpasync16(dA + row * (A_PAD * 4) + seg * 16,
                      (const char*)Xbase + (size_t)row * (CDIM * 4) + c * (KCHUNK * 4) + seg * 16);
        }
        // B: contiguous 64KB slab of pre-packed quads
        const char* srcB = (const char*)g_w1p + (size_t)c * B_STAGE;
#pragma unroll
        for (int j = 0; j < 16; j++) {
            int off = (t + j * 256) * 16;
            cpasync16(dB + off, srcB + off);
        }
    };

    load_chunk(0, 0);
    CP_COMMIT();

#pragma unroll 1
    for (int c = 0; c < NCHUNKS; c++) {
        if (c < NCHUNKS - 1) {
            load_chunk((c + 1) & 1, c + 1);
            CP_COMMIT();
            CP_WAIT(1);
        } else {
            CP_WAIT(0);
        }
        __syncthreads();

        const float* Asm = (const float*)(smem + ((c & 1) ? OFF_A1 : OFF_A0));
        const char*  Bsm = smem + ((c & 1) ? OFF_B1 : OFF_B0);

#pragma unroll
        for (int s = 0; s < 4; s++) {
            // A fragments (fp32 -> tf32 hi/lo), conflict-free lds (pad 36)
            uint32_t aHi[2][4], aLo[2][4];
#pragma unroll
            for (int mt = 0; mt < 2; mt++) {
                int r0 = wr * 32 + mt * 16 + (l >> 2);
                int c0 = s * 8 + (l & 3);
                tf32split(Asm[r0 * A_PAD + c0],           aHi[mt][0], aLo[mt][0]);
                tf32split(Asm[(r0 + 8) * A_PAD + c0],     aHi[mt][1], aLo[mt][1]);
                tf32split(Asm[r0 * A_PAD + c0 + 4],       aHi[mt][2], aLo[mt][2]);
                tf32split(Asm[(r0 + 8) * A_PAD + c0 + 4], aHi[mt][3], aLo[mt][3]);
            }
#pragma unroll
            for (int nt = 0; nt < 16; nt++) {
                // one lds.128: {hi_b0, hi_b1, lo_b0, lo_b1} for this (s, ntile)
                uint4 q = *(const uint4*)(Bsm + s * 16384 + (wc * 512 + nt * 32 + l) * 16);
#pragma unroll
                for (int mt = 0; mt < 2; mt++) {
                    mma_tf32(acc[mt][nt], aHi[mt], q.z, q.w);   // hiA * loB
                    mma_tf32(acc[mt][nt], aLo[mt], q.x, q.y);   // loA * hiB
                    mma_tf32(acc[mt][nt], aHi[mt], q.x, q.y);   // hiA * hiB
                }
            }
        }
        __syncthreads();   // stage reusable for next prefetch
    }

    // ---- epilogue: LeakyReLU -> H smem; stage W2^T; fp32 GEMM2 ----
    float* Hf  = (float*)(smem + OFF_H);
    float* sW2 = (float*)(smem + OFF_W2);
#pragma unroll
    for (int mt = 0; mt < 2; mt++) {
        int r0 = wr * 32 + mt * 16 + (l >> 2);
#pragma unroll
        for (int nt = 0; nt < 16; nt++) {
            int n0 = wc * 128 + nt * 8 + 2 * (l & 3);
            float2 p; float v;
            v = acc[mt][nt][0]; p.x = v > 0.f ? v : 0.2f * v;
            v = acc[mt][nt][1]; p.y = v > 0.f ? v : 0.2f * v;
            *(float2*)&Hf[r0 * H_STRIDE + n0] = p;
            v = acc[mt][nt][2]; p.x = v > 0.f ? v : 0.2f * v;
            v = acc[mt][nt][3]; p.y = v > 0.f ? v : 0.2f * v;
            *(float2*)&Hf[(r0 + 8) * H_STRIDE + n0] = p;
        }
    }
    for (int idx = t; idx < HID * NCLS; idx += 256) {
        int k = idx / NCLS, cc = idx - k * NCLS;
        sW2[cc * H_STRIDE + k] = W2[idx];
    }
    __syncthreads();

    // GEMM2 (fp32 SIMT, flip-safe): 128x40 = H[128][256] @ W2
    const int rg = t >> 3;     // rows rg*4 .. rg*4+3
    const int cg = t & 7;      // cols cg*5 .. cg*5+4
    float s2[4][5];
#pragma unroll
    for (int j = 0; j < 5; j++) {
        float b = bias2[cg * 5 + j];
        s2[0][j] = b; s2[1][j] = b; s2[2][j] = b; s2[3][j] = b;
    }
#pragma unroll 4
    for (int k = 0; k < HID; k += 4) {
        float4 h0 = *(const float4*)(Hf + (rg * 4 + 0) * H_STRIDE + k);
        float4 h1 = *(const float4*)(Hf + (rg * 4 + 1) * H_STRIDE + k);
        float4 h2 = *(const float4*)(Hf + (rg * 4 + 2) * H_STRIDE + k);
        float4 h3 = *(const float4*)(Hf + (rg * 4 + 3) * H_STRIDE + k);
#pragma unroll
        for (int j = 0; j < 5; j++) {
            float4 w = *(const float4*)(sW2 + (cg * 5 + j) * H_STRIDE + k);
            s2[0][j] += h0.x * w.x + h0.y * w.y + h0.z * w.z + h0.w * w.w;
            s2[1][j] += h1.x * w.x + h1.y * w.y + h1.z * w.z + h1.w * w.w;
            s2[2][j] += h2.x * w.x + h2.y * w.y + h2.z * w.z + h2.w * w.w;
            s2[3][j] += h3.x * w.x + h3.y * w.y + h3.z * w.z + h3.w * w.w;
        }
    }
    __syncthreads();   // all H reads done -> reuse for score tile

    // stage score tile [128][40] flat
#pragma unroll
    for (int rr = 0; rr < 4; rr++)
#pragma unroll
        for (int j = 0; j < 5; j++)
            Hf[(rg * 4 + rr) * NCLS + cg * 5 + j] = s2[rr][j];
    __syncthreads();

    if (!pooled) {
        float* dst = score_out + (size_t)blockRow * NCLS;
        for (int idx = t; idx < BMT * NCLS; idx += 256)
            dst[idx] = Hf[idx];
    } else if (t < BMT) {
        const float* row = &Hf[t * NCLS];
        float best = row[0]; int bi = 0;
#pragma unroll
        for (int i = 1; i < NCLS; i++)
            if (row[i] > best) { best = row[i]; bi = i; }   // first max (jnp.argmax)
        g_pred[blockRow - VROWS + t] = bi;
    }
}

// ---------------------------------------------------------------------------
// Kernel C: per-batch top-8 (desc, ties -> lower index) + gather  [R4-proven]
// ---------------------------------------------------------------------------
__global__ __launch_bounds__(256)
void select_kernel(const float* __restrict__ F0,
                   const float* __restrict__ V0,
                   const float* __restrict__ score,
                   float* __restrict__ Fnew,
                   float* __restrict__ Vnew) {
    const int b = blockIdx.x;
    const int t = threadIdx.x;
    __shared__ int sidx[SEL];

    if (t < 32) {
        int pred = g_pred[b];
        float v = (t < NVIEW) ? score[((size_t)b * NVIEW + t) * NCLS + pred] : -FLT_MAX;
        int myn = t;
#pragma unroll
        for (int sstep = 0; sstep < SEL; sstep++) {
            float bv = v; int bi = myn;
#pragma unroll
            for (int off = 16; off > 0; off >>= 1) {
                float ov = __shfl_down_sync(0xffffffffu, bv, off);
                int   oi = __shfl_down_sync(0xffffffffu, bi, off);
                if (ov > bv || (ov == bv && oi < bi)) { bv = ov; bi = oi; }
            }
            bi = __shfl_sync(0xffffffffu, bi, 0);
            if (t == 0) sidx[sstep] = bi;
            if (myn == bi) v = -FLT_MAX;
        }
    }
    __syncthreads();

    const float4* Fsrc = reinterpret_cast<const float4*>(F0);
    float4* Fdst = reinterpret_cast<float4*>(Fnew);
    for (int i = t; i < SEL * 128; i += 256) {
        int srow = i >> 7, c = i & 127;
        Fdst[((size_t)b * SEL + srow) * 128 + c] =
            Fsrc[((size_t)b * NVIEW + sidx[srow]) * 128 + c];
    }
    if (t < SEL * 3) {
        int srow = t / 3, cmp = t - srow * 3;
        Vnew[(size_t)b * (SEL * 3) + t] = V0[(size_t)b * (NVIEW * 3) + sidx[srow] * 3 + cmp];
    }
}

// ---------------------------------------------------------------------------
extern "C" void kernel_launch(void* const* d_in, const int* in_sizes, int n_in,
                              void* d_out, int out_size) {
    (void)in_sizes; (void)n_in; (void)out_size;
    const float* F0 = (const float*)d_in[0];
    const float* V0 = (const float*)d_in[1];
    const float* W1 = (const float*)d_in[2];
    const float* b1 = (const float*)d_in[3];
    const float* W2 = (const float*)d_in[4];
    const float* b2 = (const float*)d_in[5];
    float* out   = (float*)d_out;
    float* Fnew  = out + FNEW_OFF;
    float* score = out + SCORE_OFF;
    float* Vnew  = out + VNEW_OFF;

    cudaFuncSetAttribute(mlp_mma_kernel, cudaFuncAttributeMaxDynamicSharedMemorySize, SMEM_BYTES);

    pool_kernel<<<(BATCH * 128) / 256, 256>>>(F0);
    prep_w1_kernel<<<(CDIM * HID) / 256, 256>>>(W1);
    mlp_mma_kernel<<<TROWS / BMT, 256, SMEM_BYTES>>>(F0, b1, W2, b2, score);
    select_kernel<<<BATCH, 256>>>(F0, V0, score, Fnew, Vnew);
}

// round 7
// speedup vs baseline: 1.5307x; 1.0893x over previous
#include <cuda_runtime.h>
#include <cuda_bf16.h>
#include <float.h>
#include <stdint.h>

// ============================ problem constants ============================
#define BATCH   4096
#define NVIEW   20
#define CDIM    512
#define HID     256
#define NCLS    40
#define SEL     8

#define VROWS   (BATCH * NVIEW)        // 81920
#define NPOOLCTA 32                    // pooled CTAs (BATCH/128)
#define NVIEWCTA 640                   // view CTAs (VROWS/128)
#define NCTA     (NPOOLCTA + NVIEWCTA) // 672

#define FNEW_OFF   0
#define FNEW_CNT   (BATCH * SEL * CDIM)
#define SCORE_OFF  FNEW_CNT
#define SCORE_CNT  (BATCH * NVIEW * NCLS)
#define VNEW_OFF   (SCORE_OFF + SCORE_CNT)

// ============================ mma.sync GEMM config =========================
// BM=128 rows/CTA, BN=256 (full HID). 8 warps (4 row-groups x 2 col-groups).
// Warp tile 32x128 = 2 m-tiles(16) x 16 n-tiles(8). K chunks of 32 (4 ksteps).
#define BMT       128
#define KCHUNK    32
#define NCHUNKS   (CDIM / KCHUNK)      // 16
#define A_PAD     36                   // floats per row (bank-conflict-free frags)

// smem byte offsets (mainloop double-buffer)
#define OFF_A0    0
#define A_STAGE   (BMT * A_PAD * 4)    // 18432
#define OFF_A1    A_STAGE
#define OFF_B0    (2 * A_STAGE)        // 36864
#define B_STAGE   65536                // 4 ksteps x 256n x 4kk x 16B
#define OFF_B1    (OFF_B0 + B_STAGE)   // 102400
// epilogue region (reuses everything): H [128][260] fp32, then W2^T [40][260]
#define H_STRIDE  260
#define OFF_H     0
#define OFF_W2    (BMT * H_STRIDE * 4)            // 133120
#define SMEM_BYTES (OFF_W2 + NCLS * H_STRIDE * 4) // 174720

// ============================ device scratch ===============================
__device__ float    g_pooled[BATCH * CDIM];
__device__ int      g_pred[BATCH];
// W1^T split into tf32 hi/lo, packed per (kstep, n, kk) as 16B quads:
//   quad[ks][n][kk] = { hi[k0+kk, n], hi[k0+kk+4, n], lo[k0+kk, n], lo[k0+kk+4, n] }
__device__ uint32_t g_w1p[64 * 1024 * 4];

// ============================ helpers ======================================
__device__ __forceinline__ uint32_t smem_u32(const void* p) {
    uint32_t a;
    asm("{ .reg .u64 t; cvta.to.shared.u64 t, %1; cvt.u32.u64 %0, t; }" : "=r"(a) : "l"(p));
    return a;
}
__device__ __forceinline__ void tf32split(float x, uint32_t& hi, uint32_t& lo) {
    asm("cvt.rna.tf32.f32 %0, %1;" : "=r"(hi) : "f"(x));
    float r = x - __uint_as_float(hi);
    asm("cvt.rna.tf32.f32 %0, %1;" : "=r"(lo) : "f"(r));
}
__device__ __forceinline__ void mma_tf32(float* d, const uint32_t* a, uint32_t b0, uint32_t b1) {
    asm volatile(
        "mma.sync.aligned.m16n8k8.row.col.f32.tf32.tf32.f32 "
        "{%0,%1,%2,%3}, {%4,%5,%6,%7}, {%8,%9}, {%0,%1,%2,%3};"
        : "+f"(d[0]), "+f"(d[1]), "+f"(d[2]), "+f"(d[3])
        : "r"(a[0]), "r"(a[1]), "r"(a[2]), "r"(a[3]), "r"(b0), "r"(b1));
}
__device__ __forceinline__ void cpasync16(uint32_t dst, const void* src) {
    asm volatile("cp.async.cg.shared.global [%0], [%1], 16;" :: "r"(dst), "l"(src));
}
#define CP_COMMIT()  asm volatile("cp.async.commit_group;" ::: "memory")
#define CP_WAIT(N)   asm volatile("cp.async.wait_group %0;" :: "n"(N) : "memory")

// ---------------------------------------------------------------------------
// Kernel P: split W1 into tf32 hi/lo quads in the exact smem streaming layout
// ---------------------------------------------------------------------------
__global__ void prep_w1_kernel(const float* __restrict__ W1) {
    int i = blockIdx.x * blockDim.x + threadIdx.x;   // over 512*256
    int k = i >> 8;
    int n = i & 255;
    uint32_t hi, lo;
    tf32split(W1[i], hi, lo);
    int ks = k >> 3;
    int kk = k & 7;
    uint32_t* q = g_w1p + ((size_t)ks * 1024 + n * 4 + (kk & 3)) * 4;
    if (kk < 4) { q[0] = hi; q[2] = lo; }
    else        { q[1] = hi; q[3] = lo; }
}

// ---------------------------------------------------------------------------
// Kernel B: 3xTF32 mma.sync MLP with fused pooling.
// CTAs [0,32): pool own 128 batches from F0 -> g_pooled, then MLP -> argmax.
// CTAs [32,672): view rows -> score out.
// ---------------------------------------------------------------------------
__global__ __launch_bounds__(256, 1)
void mlp_mma_kernel(const float* __restrict__ F0,
                    const float* __restrict__ bias1,
                    const float* __restrict__ W2,
                    const float* __restrict__ bias2,
                    float* __restrict__ score_out) {
    extern __shared__ char smem[];
    const uint32_t sb = smem_u32(smem);
    const int t   = threadIdx.x;
    const int wid = t >> 5;
    const int l   = t & 31;
    const int wr  = wid >> 1;          // 0..3 -> rows wr*32
    const int wc  = wid & 1;           // 0..1 -> cols wc*128

    const bool pooled = (blockIdx.x < NPOOLCTA);
    const float* Xbase;
    int blockRow = 0;                  // view-row base (view CTAs only)

    if (pooled) {
        // ---- phase 0: pool this CTA's 128 batches (self-produced, race-free) ----
        const int b0 = blockIdx.x * BMT;             // first batch
        float4* dstP = reinterpret_cast<float4*>(g_pooled) + (size_t)b0 * 128;
        const float4* srcP = reinterpret_cast<const float4*>(F0) + (size_t)b0 * (NVIEW * 128);
        const float inv = 1.0f / 20.0f;
        for (int i = t; i < BMT * 128; i += 256) {   // 16384 float4
            int bb = i >> 7, c4 = i & 127;
            const float4* p = srcP + (size_t)bb * (NVIEW * 128) + c4;
            float4 s = p[0];
#pragma unroll
            for (int n = 1; n < NVIEW; n++) {
                float4 q = p[n * 128];
                s.x += q.x; s.y += q.y; s.z += q.z; s.w += q.w;
            }
            s.x *= inv; s.y *= inv; s.z *= inv; s.w *= inv;
            dstP[i] = s;
        }
        __syncthreads();   // block-wide global visibility guaranteed across this
        Xbase = g_pooled + (size_t)b0 * CDIM;
    } else {
        blockRow = (blockIdx.x - NPOOLCTA) * BMT;
        Xbase = F0 + (size_t)blockRow * CDIM;
    }

    // ---- accumulators, initialized from bias1 (per-column) ----
    float acc[2][16][4];
#pragma unroll
    for (int nt = 0; nt < 16; nt++) {
        int n0 = wc * 128 + nt * 8 + 2 * (l & 3);
        float b0v = bias1[n0], b1v = bias1[n0 + 1];
#pragma unroll
        for (int mt = 0; mt < 2; mt++) {
            acc[mt][nt][0] = b0v; acc[mt][nt][1] = b1v;
            acc[mt][nt][2] = b0v; acc[mt][nt][3] = b1v;
        }
    }

    // ---- async chunk loader ----
    auto load_chunk = [&](int stage, int c) {
        uint32_t dA = sb + (stage ? OFF_A1 : OFF_A0);
        uint32_t dB = sb + (stage ? OFF_B1 : OFF_B0);
#pragma unroll
        for (int j = 0; j < 4; j++) {
            int o = t + j * 256;
            int row = o >> 3, seg = o & 7;
            cpasync16(dA + row * (A_PAD * 4) + seg * 16,
                      (const char*)Xbase + (size_t)row * (CDIM * 4) + c * (KCHUNK * 4) + seg * 16);
        }
        const char* srcB = (const char*)g_w1p + (size_t)c * B_STAGE;
#pragma unroll
        for (int j = 0; j < 16; j++) {
            int off = (t + j * 256) * 16;
            cpasync16(dB + off, srcB + off);
        }
    };

    load_chunk(0, 0);
    CP_COMMIT();

#pragma unroll 1
    for (int c = 0; c < NCHUNKS; c++) {
        if (c < NCHUNKS - 1) {
            load_chunk((c + 1) & 1, c + 1);
            CP_COMMIT();
            CP_WAIT(1);
        } else {
            CP_WAIT(0);
        }
        __syncthreads();

        const float* Asm = (const float*)(smem + ((c & 1) ? OFF_A1 : OFF_A0));
        const char*  Bsm = smem + ((c & 1) ? OFF_B1 : OFF_B0);

#pragma unroll
        for (int s = 0; s < 4; s++) {
            uint32_t aHi[2][4], aLo[2][4];
#pragma unroll
            for (int mt = 0; mt < 2; mt++) {
                int r0 = wr * 32 + mt * 16 + (l >> 2);
                int c0 = s * 8 + (l & 3);
                tf32split(Asm[r0 * A_PAD + c0],           aHi[mt][0], aLo[mt][0]);
                tf32split(Asm[(r0 + 8) * A_PAD + c0],     aHi[mt][1], aLo[mt][1]);
                tf32split(Asm[r0 * A_PAD + c0 + 4],       aHi[mt][2], aLo[mt][2]);
                tf32split(Asm[(r0 + 8) * A_PAD + c0 + 4], aHi[mt][3], aLo[mt][3]);
            }
#pragma unroll
            for (int nt = 0; nt < 16; nt++) {
                uint4 q = *(const uint4*)(Bsm + s * 16384 + (wc * 512 + nt * 32 + l) * 16);
#pragma unroll
                for (int mt = 0; mt < 2; mt++) {
                    mma_tf32(acc[mt][nt], aHi[mt], q.z, q.w);   // hiA * loB
                    mma_tf32(acc[mt][nt], aLo[mt], q.x, q.y);   // loA * hiB
                    mma_tf32(acc[mt][nt], aHi[mt], q.x, q.y);   // hiA * hiB
                }
            }
        }
        __syncthreads();
    }

    // ---- epilogue: LeakyReLU -> H smem; stage W2^T; fp32 GEMM2 ----
    float* Hf  = (float*)(smem + OFF_H);
    float* sW2 = (float*)(smem + OFF_W2);
#pragma unroll
    for (int mt = 0; mt < 2; mt++) {
        int r0 = wr * 32 + mt * 16 + (l >> 2);
#pragma unroll
        for (int nt = 0; nt < 16; nt++) {
            int n0 = wc * 128 + nt * 8 + 2 * (l & 3);
            float2 p; float v;
            v = acc[mt][nt][0]; p.x = v > 0.f ? v : 0.2f * v;
            v = acc[mt][nt][1]; p.y = v > 0.f ? v : 0.2f * v;
            *(float2*)&Hf[r0 * H_STRIDE + n0] = p;
            v = acc[mt][nt][2]; p.x = v > 0.f ? v : 0.2f * v;
            v = acc[mt][nt][3]; p.y = v > 0.f ? v : 0.2f * v;
            *(float2*)&Hf[(r0 + 8) * H_STRIDE + n0] = p;
        }
    }
    for (int idx = t; idx < HID * NCLS; idx += 256) {
        int k = idx / NCLS, cc = idx - k * NCLS;
        sW2[cc * H_STRIDE + k] = W2[idx];
    }
    __syncthreads();

    // GEMM2 (fp32 SIMT, flip-safe): 128x40 = H[128][256] @ W2
    const int rg = t >> 3;
    const int cg = t & 7;
    float s2[4][5];
#pragma unroll
    for (int j = 0; j < 5; j++) {
        float b = bias2[cg * 5 + j];
        s2[0][j] = b; s2[1][j] = b; s2[2][j] = b; s2[3][j] = b;
    }
#pragma unroll 4
    for (int k = 0; k < HID; k += 4) {
        float4 h0 = *(const float4*)(Hf + (rg * 4 + 0) * H_STRIDE + k);
        float4 h1 = *(const float4*)(Hf + (rg * 4 + 1) * H_STRIDE + k);
        float4 h2 = *(const float4*)(Hf + (rg * 4 + 2) * H_STRIDE + k);
        float4 h3 = *(const float4*)(Hf + (rg * 4 + 3) * H_STRIDE + k);
#pragma unroll
        for (int j = 0; j < 5; j++) {
            float4 w = *(const float4*)(sW2 + (cg * 5 + j) * H_STRIDE + k);
            s2[0][j] += h0.x * w.x + h0.y * w.y + h0.z * w.z + h0.w * w.w;
            s2[1][j] += h1.x * w.x + h1.y * w.y + h1.z * w.z + h1.w * w.w;
            s2[2][j] += h2.x * w.x + h2.y * w.y + h2.z * w.z + h2.w * w.w;
            s2[3][j] += h3.x * w.x + h3.y * w.y + h3.z * w.z + h3.w * w.w;
        }
    }
    __syncthreads();

    // stage score tile [128][40] flat
#pragma unroll
    for (int rr = 0; rr < 4; rr++)
#pragma unroll
        for (int j = 0; j < 5; j++)
            Hf[(rg * 4 + rr) * NCLS + cg * 5 + j] = s2[rr][j];
    __syncthreads();

    if (!pooled) {
        float* dst = score_out + (size_t)blockRow * NCLS;
        for (int idx = t; idx < BMT * NCLS; idx += 256)
            dst[idx] = Hf[idx];
    } else if (t < BMT) {
        const float* row = &Hf[t * NCLS];
        float best = row[0]; int bi = 0;
#pragma unroll
        for (int i = 1; i < NCLS; i++)
            if (row[i] > best) { best = row[i]; bi = i; }   // first max (jnp.argmax)
        g_pred[blockIdx.x * BMT + t] = bi;
    }
}

// ---------------------------------------------------------------------------
// Kernel C: 8 batches/block. Warp w: top-8 for batch blockIdx*8+w.
// Then all 256 threads gather 64 rows (MLP ~32) + vertices.
// ---------------------------------------------------------------------------
__global__ __launch_bounds__(256)
void select_kernel(const float* __restrict__ F0,
                   const float* __restrict__ V0,
                   const float* __restrict__ score,
                   float* __restrict__ Fnew,
                   float* __restrict__ Vnew) {
    const int t = threadIdx.x;
    const int w = t >> 5;
    const int lane = t & 31;
    const int b = blockIdx.x * 8 + w;
    __shared__ int sidx[8][SEL];

    {
        int pred = g_pred[b];
        float v = (lane < NVIEW) ? score[((size_t)b * NVIEW + lane) * NCLS + pred] : -FLT_MAX;
        int myn = lane;
#pragma unroll
        for (int sstep = 0; sstep < SEL; sstep++) {
            float bv = v; int bi = myn;
#pragma unroll
            for (int off = 16; off > 0; off >>= 1) {
                float ov = __shfl_down_sync(0xffffffffu, bv, off);
                int   oi = __shfl_down_sync(0xffffffffu, bi, off);
                if (ov > bv || (ov == bv && oi < bi)) { bv = ov; bi = oi; }
            }
            bi = __shfl_sync(0xffffffffu, bi, 0);
            if (lane == 0) sidx[w][sstep] = bi;
            if (myn == bi) v = -FLT_MAX;
        }
    }
    __syncthreads();

    // F_new gather: 8 batches x 8 rows x 128 float4 = 8192 float4 (32/thread)
    const float4* Fsrc = reinterpret_cast<const float4*>(F0);
    float4* Fdst = reinterpret_cast<float4*>(Fnew);
#pragma unroll
    for (int j = 0; j < 32; j++) {
        int i = t + j * 256;
        int bl = i >> 10, srow = (i >> 7) & 7, c = i & 127;
        int bb = blockIdx.x * 8 + bl;
        Fdst[((size_t)bb * SEL + srow) * 128 + c] =
            Fsrc[((size_t)bb * NVIEW + sidx[bl][srow]) * 128 + c];
    }
    // vertices: 8 batches x 8 x 3 = 192 floats
    if (t < 8 * SEL * 3) {
        int bl = t / (SEL * 3), r = t % (SEL * 3);
        int srow = r / 3, cmp = r - srow * 3;
        int bb = blockIdx.x * 8 + bl;
        Vnew[(size_t)bb * (SEL * 3) + r] = V0[(size_t)bb * (NVIEW * 3) + sidx[bl][srow] * 3 + cmp];
    }
}

// ---------------------------------------------------------------------------
extern "C" void kernel_launch(void* const* d_in, const int* in_sizes, int n_in,
                              void* d_out, int out_size) {
    (void)in_sizes; (void)n_in; (void)out_size;
    const float* F0 = (const float*)d_in[0];
    const float* V0 = (const float*)d_in[1];
    const float* W1 = (const float*)d_in[2];
    const float* b1 = (const float*)d_in[3];
    const float* W2 = (const float*)d_in[4];
    const float* b2 = (const float*)d_in[5];
    float* out   = (float*)d_out;
    float* Fnew  = out + FNEW_OFF;
    float* score = out + SCORE_OFF;
    float* Vnew  = out + VNEW_OFF;

    cudaFuncSetAttribute(mlp_mma_kernel, cudaFuncAttributeMaxDynamicSharedMemorySize, SMEM_BYTES);

    prep_w1_kernel<<<(CDIM * HID) / 256, 256>>>(W1);
    mlp_mma_kernel<<<NCTA, 256, SMEM_BYTES>>>(F0, b1, W2, b2, score);
    select_kernel<<<BATCH / 8, 256>>>(F0, V0, score, Fnew, Vnew);
}

// round 8
// speedup vs baseline: 2.3199x; 1.5156x over previous
#include <cuda_runtime.h>
#include <cuda_fp16.h>
#include <cuda_bf16.h>
#include <float.h>
#include <stdint.h>

// ============================ problem constants ============================
#define BATCH   4096
#define NVIEW   20
#define CDIM    512
#define HID     256
#define NCLS    40
#define SEL     8

#define VROWS   (BATCH * NVIEW)        // 81920
#define NPOOLCTA 32                    // pooled CTAs (BATCH/128)
#define NVIEWCTA 640                   // view CTAs
#define NCTA     (NPOOLCTA + NVIEWCTA) // 672

#define FNEW_OFF   0
#define FNEW_CNT   (BATCH * SEL * CDIM)
#define SCORE_OFF  FNEW_CNT
#define SCORE_CNT  (BATCH * NVIEW * NCLS)
#define VNEW_OFF   (SCORE_OFF + SCORE_CNT)

// ============================ mma.sync GEMM config =========================
// BM=128 rows/CTA, BN=256. 8 warps (4 row x 2 col groups). Warp tile 32x128.
// fp16 m16n8k16, 2-way split, 3 passes. K chunks of 32 (2 k16-steps).
// Global scaling: X*16, W*256 -> acc = 4096 * (x@W); epilogue * 1/4096.
#define BMT       128
#define KCHUNK    32
#define NCHUNKS   (CDIM / KCHUNK)      // 16
#define A_PAD     40                   // floats/row: LDS.64 conflict-free
#define XSCALE    16.0f
#define WSCALE    256.0f
#define INVSCALE  (1.0f / 4096.0f)

// smem byte offsets (mainloop double-buffer)
#define OFF_A0    0
#define A_STAGE   (BMT * A_PAD * 4)    // 20480
#define OFF_A1    A_STAGE
#define OFF_B0    (2 * A_STAGE)        // 40960
#define B_STAGE   32768                // 2 k16-steps x 256n x 4kk x 16B
#define OFF_B1    (OFF_B0 + B_STAGE)   // 73728
// epilogue region (reuses everything): H [128][260] fp32, then W2^T [40][260]
#define H_STRIDE  260
#define OFF_H     0
#define OFF_W2    (BMT * H_STRIDE * 4)            // 133120
#define SMEM_BYTES (OFF_W2 + NCLS * H_STRIDE * 4) // 174720

// ============================ device scratch ===============================
__device__ float    g_pooled[BATCH * CDIM];
__device__ int      g_pred[BATCH];
// W1^T fp16 hi/lo quads: [ks16 0..31][n 0..255][kk 0..3] x 16B
//   quad = { b0hi, b1hi, b0lo, b1lo }; word = half2 {k_even(lo), k_odd(hi)}
//   b0: k = 16ks + 2kk + {0,1};  b1: k = 16ks + 8 + 2kk + {0,1}
__device__ uint32_t g_w1p[32 * 256 * 4 * 4];   // 512 KB

// ============================ helpers ======================================
__device__ __forceinline__ uint32_t smem_u32(const void* p) {
    uint32_t a;
    asm("{ .reg .u64 t; cvta.to.shared.u64 t, %1; cvt.u32.u64 %0, t; }" : "=r"(a) : "l"(p));
    return a;
}
__device__ __forceinline__ void mma_f16(float* d, const uint32_t* a, uint32_t b0, uint32_t b1) {
    asm volatile(
        "mma.sync.aligned.m16n8k16.row.col.f32.f16.f16.f32 "
        "{%0,%1,%2,%3}, {%4,%5,%6,%7}, {%8,%9}, {%0,%1,%2,%3};"
        : "+f"(d[0]), "+f"(d[1]), "+f"(d[2]), "+f"(d[3])
        : "r"(a[0]), "r"(a[1]), "r"(a[2]), "r"(a[3]), "r"(b0), "r"(b1));
}
__device__ __forceinline__ void cpasync16(uint32_t dst, const void* src) {
    asm volatile("cp.async.cg.shared.global [%0], [%1], 16;" :: "r"(dst), "l"(src));
}
#define CP_COMMIT()  asm volatile("cp.async.commit_group;" ::: "memory")
#define CP_WAIT(N)   asm volatile("cp.async.wait_group %0;" :: "n"(N) : "memory")

// scale by XSCALE, split to fp16 hi/lo, pack pairs (k_even -> low half)
__device__ __forceinline__ void pack_split(float2 v, uint32_t& hi, uint32_t& lo) {
    float x0 = v.x * XSCALE, x1 = v.y * XSCALE;
    __half h0 = __float2half_rn(x0), h1 = __float2half_rn(x1);
    __half2 hp = __halves2half2(h0, h1);
    hi = *reinterpret_cast<uint32_t*>(&hp);
    float r0 = x0 - __half2float(h0), r1 = x1 - __half2float(h1);
    __half2 lp = __halves2half2(__float2half_rn(r0), __float2half_rn(r1));
    lo = *reinterpret_cast<uint32_t*>(&lp);
}

// ---------------------------------------------------------------------------
// Kernel P: split W1*256 into fp16 hi/lo quads in the streaming layout
// ---------------------------------------------------------------------------
__global__ void prep_w1_kernel(const float* __restrict__ W1) {
    int i = blockIdx.x * blockDim.x + threadIdx.x;   // over 512*256
    int k = i >> 8;
    int n = i & 255;
    float w = W1[i] * WSCALE;
    __half hi = __float2half_rn(w);
    float r = w - __half2float(hi);
    __half lo = __float2half_rn(r);
    int ks   = k >> 4;
    int kpos = k & 15;
    int kk   = (kpos & 7) >> 1;
    int breg = kpos >> 3;
    int hsel = kpos & 1;
    uint16_t* q = reinterpret_cast<uint16_t*>(g_w1p) + ((size_t)(ks * 256 + n) * 4 + kk) * 8;
    q[breg * 2 + hsel]     = *reinterpret_cast<uint16_t*>(&hi);
    q[4 + breg * 2 + hsel] = *reinterpret_cast<uint16_t*>(&lo);
}

// ---------------------------------------------------------------------------
// Kernel B: 3-pass fp16 mma.sync MLP with fused pooling.
// CTAs [0,32): pool own 128 batches -> g_pooled, MLP -> argmax.
// CTAs [32,672): view rows -> score out.
// ---------------------------------------------------------------------------
__global__ __launch_bounds__(256, 1)
void mlp_mma_kernel(const float* __restrict__ F0,
                    const float* __restrict__ bias1,
                    const float* __restrict__ W2,
                    const float* __restrict__ bias2,
                    float* __restrict__ score_out) {
    extern __shared__ char smem[];
    const uint32_t sb = smem_u32(smem);
    const int t   = threadIdx.x;
    const int wid = t >> 5;
    const int l   = t & 31;
    const int wr  = wid >> 1;          // 0..3 -> rows wr*32
    const int wc  = wid & 1;           // 0..1 -> cols wc*128

    const bool pooled = (blockIdx.x < NPOOLCTA);
    const float* Xbase;
    int blockRow = 0;

    if (pooled) {
        // phase 0: pool this CTA's 128 batches (self-produced -> race-free)
        const int b0 = blockIdx.x * BMT;
        float4* dstP = reinterpret_cast<float4*>(g_pooled) + (size_t)b0 * 128;
        const float4* srcP = reinterpret_cast<const float4*>(F0) + (size_t)b0 * (NVIEW * 128);
        const float inv = 1.0f / 20.0f;
        for (int i = t; i < BMT * 128; i += 256) {
            int bb = i >> 7, c4 = i & 127;
            const float4* p = srcP + (size_t)bb * (NVIEW * 128) + c4;
            float4 s = p[0];
#pragma unroll
            for (int n = 1; n < NVIEW; n++) {
                float4 q = p[n * 128];
                s.x += q.x; s.y += q.y; s.z += q.z; s.w += q.w;
            }
            s.x *= inv; s.y *= inv; s.z *= inv; s.w *= inv;
            dstP[i] = s;
        }
        __syncthreads();
        Xbase = g_pooled + (size_t)b0 * CDIM;
    } else {
        blockRow = (blockIdx.x - NPOOLCTA) * BMT;
        Xbase = F0 + (size_t)blockRow * CDIM;
    }

    // ---- accumulators (bias added in epilogue after unscaling) ----
    float acc[2][16][4];
#pragma unroll
    for (int nt = 0; nt < 16; nt++)
#pragma unroll
        for (int mt = 0; mt < 2; mt++) {
            acc[mt][nt][0] = 0.f; acc[mt][nt][1] = 0.f;
            acc[mt][nt][2] = 0.f; acc[mt][nt][3] = 0.f;
        }

    // ---- async chunk loader ----
    auto load_chunk = [&](int stage, int c) {
        uint32_t dA = sb + (stage ? OFF_A1 : OFF_A0);
        uint32_t dB = sb + (stage ? OFF_B1 : OFF_B0);
        // A: 128 rows x 32 floats (8 x 16B per row)
#pragma unroll
        for (int j = 0; j < 4; j++) {
            int o = t + j * 256;
            int row = o >> 3, seg = o & 7;
            cpasync16(dA + row * (A_PAD * 4) + seg * 16,
                      (const char*)Xbase + (size_t)row * (CDIM * 4) + c * (KCHUNK * 4) + seg * 16);
        }
        // B: 32KB contiguous slab (k16-steps 2c, 2c+1)
        const char* srcB = (const char*)g_w1p + (size_t)c * B_STAGE;
#pragma unroll
        for (int j = 0; j < 8; j++) {
            int off = (t + j * 256) * 16;
            cpasync16(dB + off, srcB + off);
        }
    };

    load_chunk(0, 0);
    CP_COMMIT();

#pragma unroll 1
    for (int c = 0; c < NCHUNKS; c++) {
        if (c < NCHUNKS - 1) {
            load_chunk((c + 1) & 1, c + 1);
            CP_COMMIT();
            CP_WAIT(1);
        } else {
            CP_WAIT(0);
        }
        __syncthreads();

        const float* Asm = (const float*)(smem + ((c & 1) ? OFF_A1 : OFF_A0));
        const char*  Bsm = smem + ((c & 1) ? OFF_B1 : OFF_B0);

#pragma unroll
        for (int s = 0; s < 2; s++) {                 // two k16-steps
            uint32_t aHi[2][4], aLo[2][4];
#pragma unroll
            for (int mt = 0; mt < 2; mt++) {
                int r0 = wr * 32 + mt * 16 + (l >> 2);
                int c0 = s * 16 + 2 * (l & 3);
                const float* Ar  = Asm + r0 * A_PAD;
                const float* Ar8 = Asm + (r0 + 8) * A_PAD;
                pack_split(*(const float2*)&Ar[c0],      aHi[mt][0], aLo[mt][0]);
                pack_split(*(const float2*)&Ar8[c0],     aHi[mt][1], aLo[mt][1]);
                pack_split(*(const float2*)&Ar[c0 + 8],  aHi[mt][2], aLo[mt][2]);
                pack_split(*(const float2*)&Ar8[c0 + 8], aHi[mt][3], aLo[mt][3]);
            }
#pragma unroll
            for (int nt = 0; nt < 16; nt++) {
                // one lds.128: {b0hi, b1hi, b0lo, b1lo}
                uint4 q = *(const uint4*)(Bsm + s * 16384 + (wc * 512 + nt * 32 + l) * 16);
#pragma unroll
                for (int mt = 0; mt < 2; mt++) {
                    mma_f16(acc[mt][nt], aHi[mt], q.z, q.w);   // hiA * loB
                    mma_f16(acc[mt][nt], aLo[mt], q.x, q.y);   // loA * hiB
                    mma_f16(acc[mt][nt], aHi[mt], q.x, q.y);   // hiA * hiB
                }
            }
        }
        __syncthreads();
    }

    // ---- epilogue: unscale + bias + LeakyReLU -> H smem; stage W2^T ----
    float* Hf  = (float*)(smem + OFF_H);
    float* sW2 = (float*)(smem + OFF_W2);
#pragma unroll
    for (int mt = 0; mt < 2; mt++) {
        int r0 = wr * 32 + mt * 16 + (l >> 2);
#pragma unroll
        for (int nt = 0; nt < 16; nt++) {
            int n0 = wc * 128 + nt * 8 + 2 * (l & 3);
            float b0v = bias1[n0], b1v = bias1[n0 + 1];
            float2 p; float v;
            v = acc[mt][nt][0] * INVSCALE + b0v; p.x = v > 0.f ? v : 0.2f * v;
            v = acc[mt][nt][1] * INVSCALE + b1v; p.y = v > 0.f ? v : 0.2f * v;
            *(float2*)&Hf[r0 * H_STRIDE + n0] = p;
            v = acc[mt][nt][2] * INVSCALE + b0v; p.x = v > 0.f ? v : 0.2f * v;
            v = acc[mt][nt][3] * INVSCALE + b1v; p.y = v > 0.f ? v : 0.2f * v;
            *(float2*)&Hf[(r0 + 8) * H_STRIDE + n0] = p;
        }
    }
    for (int idx = t; idx < HID * NCLS; idx += 256) {
        int k = idx / NCLS, cc = idx - k * NCLS;
        sW2[cc * H_STRIDE + k] = W2[idx];
    }
    __syncthreads();

    // GEMM2 (fp32 SIMT, flip-safe): 128x40 = H[128][256] @ W2
    const int rg = t >> 3;
    const int cg = t & 7;
    float s2[4][5];
#pragma unroll
    for (int j = 0; j < 5; j++) {
        float b = bias2[cg * 5 + j];
        s2[0][j] = b; s2[1][j] = b; s2[2][j] = b; s2[3][j] = b;
    }
#pragma unroll 4
    for (int k = 0; k < HID; k += 4) {
        float4 h0 = *(const float4*)(Hf + (rg * 4 + 0) * H_STRIDE + k);
        float4 h1 = *(const float4*)(Hf + (rg * 4 + 1) * H_STRIDE + k);
        float4 h2 = *(const float4*)(Hf + (rg * 4 + 2) * H_STRIDE + k);
        float4 h3 = *(const float4*)(Hf + (rg * 4 + 3) * H_STRIDE + k);
#pragma unroll
        for (int j = 0; j < 5; j++) {
            float4 w = *(const float4*)(sW2 + (cg * 5 + j) * H_STRIDE + k);
            s2[0][j] += h0.x * w.x + h0.y * w.y + h0.z * w.z + h0.w * w.w;
            s2[1][j] += h1.x * w.x + h1.y * w.y + h1.z * w.z + h1.w * w.w;
            s2[2][j] += h2.x * w.x + h2.y * w.y + h2.z * w.z + h2.w * w.w;
            s2[3][j] += h3.x * w.x + h3.y * w.y + h3.z * w.z + h3.w * w.w;
        }
    }
    __syncthreads();

    // stage score tile [128][40] flat
#pragma unroll
    for (int rr = 0; rr < 4; rr++)
#pragma unroll
        for (int j = 0; j < 5; j++)
            Hf[(rg * 4 + rr) * NCLS + cg * 5 + j] = s2[rr][j];
    __syncthreads();

    if (!pooled) {
        float* dst = score_out + (size_t)blockRow * NCLS;
        for (int idx = t; idx < BMT * NCLS; idx += 256)
            dst[idx] = Hf[idx];
    } else if (t < BMT) {
        const float* row = &Hf[t * NCLS];
        float best = row[0]; int bi = 0;
#pragma unroll
        for (int i = 1; i < NCLS; i++)
            if (row[i] > best) { best = row[i]; bi = i; }   // first max (jnp.argmax)
        g_pred[blockIdx.x * BMT + t] = bi;
    }
}

// ---------------------------------------------------------------------------
// Kernel C: 8 batches/block; warp w does top-8 for its batch, then all 256
// threads gather 64 rows (high MLP) + vertices.  [R7-proven]
// ---------------------------------------------------------------------------
__global__ __launch_bounds__(256)
void select_kernel(const float* __restrict__ F0,
                   const float* __restrict__ V0,
                   const float* __restrict__ score,
                   float* __restrict__ Fnew,
                   float* __restrict__ Vnew) {
    const int t = threadIdx.x;
    const int w = t >> 5;
    const int lane = t & 31;
    const int b = blockIdx.x * 8 + w;
    __shared__ int sidx[8][SEL];

    {
        int pred = g_pred[b];
        float v = (lane < NVIEW) ? score[((size_t)b * NVIEW + lane) * NCLS + pred] : -FLT_MAX;
        int myn = lane;
#pragma unroll
        for (int sstep = 0; sstep < SEL; sstep++) {
            float bv = v; int bi = myn;
#pragma unroll
            for (int off = 16; off > 0; off >>= 1) {
                float ov = __shfl_down_sync(0xffffffffu, bv, off);
                int   oi = __shfl_down_sync(0xffffffffu, bi, off);
                if (ov > bv || (ov == bv && oi < bi)) { bv = ov; bi = oi; }
            }
            bi = __shfl_sync(0xffffffffu, bi, 0);
            if (lane == 0) sidx[w][sstep] = bi;
            if (myn == bi) v = -FLT_MAX;
        }
    }
    __syncthreads();

    const float4* Fsrc = reinterpret_cast<const float4*>(F0);
    float4* Fdst = reinterpret_cast<float4*>(Fnew);
#pragma unroll
    for (int j = 0; j < 32; j++) {
        int i = t + j * 256;
        int bl = i >> 10, srow = (i >> 7) & 7, c = i & 127;
        int bb = blockIdx.x * 8 + bl;
        Fdst[((size_t)bb * SEL + srow) * 128 + c] =
            Fsrc[((size_t)bb * NVIEW + sidx[bl][srow]) * 128 + c];
    }
    if (t < 8 * SEL * 3) {
        int bl = t / (SEL * 3), r = t % (SEL * 3);
        int srow = r / 3, cmp = r - srow * 3;
        int bb = blockIdx.x * 8 + bl;
        Vnew[(size_t)bb * (SEL * 3) + r] = V0[(size_t)bb * (NVIEW * 3) + sidx[bl][srow] * 3 + cmp];
    }
}

// ---------------------------------------------------------------------------
extern "C" void kernel_launch(void* const* d_in, const int* in_sizes, int n_in,
                              void* d_out, int out_size) {
    (void)in_sizes; (void)n_in; (void)out_size;
    const float* F0 = (const float*)d_in[0];
    const float* V0 = (const float*)d_in[1];
    const float* W1 = (const float*)d_in[2];
    const float* b1 = (const float*)d_in[3];
    const float* W2 = (const float*)d_in[4];
    const float* b2 = (const float*)d_in[5];
    float* out   = (float*)d_out;
    float* Fnew  = out + FNEW_OFF;
    float* score = out + SCORE_OFF;
    float* Vnew  = out + VNEW_OFF;

    cudaFuncSetAttribute(mlp_mma_kernel, cudaFuncAttributeMaxDynamicSharedMemorySize, SMEM_BYTES);

    prep_w1_kernel<<<(CDIM * HID) / 256, 256>>>(W1);
    mlp_mma_kernel<<<NCTA, 256, SMEM_BYTES>>>(F0, b1, W2, b2, score);
    select_kernel<<<BATCH / 8, 256>>>(F0, V0, score, Fnew, Vnew);
}